// round 2
// baseline (speedup 1.0000x reference)
#include <cuda_runtime.h>

#define DFEAT 128
#define NMAX  50000

// scratch (no allocations allowed) ------------------------------------------
__device__ __align__(16) float g_h[NMAX * DFEAT];   // post-GEMM features, 25.6 MB
__device__ __align__(16) float g_deg[NMAX];
__device__ __align__(16) float g_dinv[NMAX];

__device__ __forceinline__ void red_add_v4(float* addr, float4 v) {
    asm volatile("red.global.add.v4.f32 [%0], {%1,%2,%3,%4};"
                 :: "l"(addr), "f"(v.x), "f"(v.y), "f"(v.z), "f"(v.w)
                 : "memory");
}

#define WT_STRIDE 132   // multiple of 4 -> LDS.128-aligned rows

// ---------------------------------------------------------------------------
__global__ void k_zero(float* __restrict__ out, int n_out, int n_nodes) {
    int i = blockIdx.x * blockDim.x + threadIdx.x;
    int stride = gridDim.x * blockDim.x;
    for (int idx = i; idx < n_out; idx += stride) out[idx] = 0.f;
    for (int idx = i; idx < n_nodes; idx += stride) g_deg[idx] = 0.f;
}

__global__ void k_degree(const int* __restrict__ ei, int E) {
    int e = blockIdx.x * blockDim.x + threadIdx.x;
    if (e >= E) return;
    atomicAdd(&g_deg[ei[e]], 1.f);       // src
    atomicAdd(&g_deg[ei[E + e]], 1.f);   // dst
}

__global__ void k_dinv(int N) {
    int i = blockIdx.x * blockDim.x + threadIdx.x;
    if (i < N) g_dinv[i] = rsqrtf(fmaxf(g_deg[i], 1.0f));
}

// ---------------------------------------------------------------------------
// Fused logmap0 + GEMM: h = logmap0(x) @ W^T + b
// Block: 256 threads, 32 rows. Shared: W^T (128 x WT_STRIDE) + x tile (32x128).
__global__ void k_logmap_gemm(const float* __restrict__ x,
                              const float* __restrict__ W,
                              const float* __restrict__ b, int N) {
    extern __shared__ float sm[];
    float* wt = sm;                       // [128][WT_STRIDE] transposed W
    float* xs = sm + 128 * WT_STRIDE;     // [32][128] tangent x rows
    const int tid  = threadIdx.x;
    const int row0 = blockIdx.x * 32;

    // load W transposed (coalesced gmem read)
    for (int idx = tid; idx < 128 * 128; idx += 256) {
        int o = idx >> 7, k = idx & 127;
        wt[k * WT_STRIDE + o] = W[idx];
    }
    // load x rows (float4)
    const float4* x4  = (const float4*)x;
    float4*       xs4 = (float4*)xs;
    for (int i = tid; i < 32 * 32; i += 256) {
        int r = i >> 5, c = i & 31;
        int row = row0 + r;
        xs4[r * 32 + c] = (row < N) ? x4[row * 32 + c] : make_float4(0.f, 0.f, 0.f, 0.f);
    }
    __syncthreads();

    // logmap0 per row: 8 warps x 4 rows
    const int warp = tid >> 5, lane = tid & 31;
#pragma unroll
    for (int rr = 0; rr < 4; rr++) {
        int r = warp * 4 + rr;
        float4 v = xs4[r * 32 + lane];
        float s = v.x * v.x + v.y * v.y + v.z * v.z + v.w * v.w;
#pragma unroll
        for (int off = 16; off; off >>= 1) s += __shfl_xor_sync(0xFFFFFFFFu, s, off);
        float norm = sqrtf(s);
        float nc = fminf(fmaxf(norm, 1e-15f), 1.0f - 1e-5f);
        float scale = atanhf(nc) / fmaxf(norm, 1e-15f);
        v.x *= scale; v.y *= scale; v.z *= scale; v.w *= scale;
        xs4[r * 32 + lane] = v;
    }
    __syncthreads();

    // GEMM: each thread computes 4 rows x 4 cols
    const int co = (tid & 31) * 4;     // output col group
    const int ro = (tid >> 5) * 4;     // row group within tile
    float acc[4][4] = {};
#pragma unroll 4
    for (int k = 0; k < 128; k++) {
        float4 wv = *(const float4*)&wt[k * WT_STRIDE + co];
#pragma unroll
        for (int i = 0; i < 4; i++) {
            float xv = xs[(ro + i) * 128 + k];   // warp-uniform broadcast
            acc[i][0] += xv * wv.x;
            acc[i][1] += xv * wv.y;
            acc[i][2] += xv * wv.z;
            acc[i][3] += xv * wv.w;
        }
    }
    float4 bv = *(const float4*)&b[co];
    float4* h4 = (float4*)g_h;
#pragma unroll
    for (int i = 0; i < 4; i++) {
        int row = row0 + ro + i;
        if (row < N) {
            float4 o;
            o.x = acc[i][0] + bv.x;
            o.y = acc[i][1] + bv.y;
            o.z = acc[i][2] + bv.z;
            o.w = acc[i][3] + bv.w;
            h4[row * 32 + (co >> 2)] = o;
        }
    }
}

// ---------------------------------------------------------------------------
// Edge scatter: one warp per edge. lane = one float4 of the 128-dim feature.
__global__ void k_scatter(const int* __restrict__ ei, float* __restrict__ out, int E) {
    int gw = (blockIdx.x * blockDim.x + threadIdx.x) >> 5;
    int lane = threadIdx.x & 31;
    if (gw >= E) return;
    int src = ei[gw];
    int dst = ei[E + gw];
    float coef = g_dinv[src] * g_dinv[dst];
    const float4* h4 = (const float4*)g_h;
    float4 v = h4[src * 32 + lane];
    v.x *= coef; v.y *= coef; v.z *= coef; v.w *= coef;
    float4* o4 = (float4*)out;
    red_add_v4((float*)&o4[dst * 32 + lane], v);
}

// ---------------------------------------------------------------------------
// expmap0 in-place on out: one warp per node.
__global__ void k_expmap(float* __restrict__ out, int N) {
    int gw = (blockIdx.x * blockDim.x + threadIdx.x) >> 5;
    int lane = threadIdx.x & 31;
    if (gw >= N) return;
    float4* o4 = (float4*)out;
    float4 v = o4[gw * 32 + lane];
    float s = v.x * v.x + v.y * v.y + v.z * v.z + v.w * v.w;
#pragma unroll
    for (int off = 16; off; off >>= 1) s += __shfl_xor_sync(0xFFFFFFFFu, s, off);
    float norm = sqrtf(s);
    float scale = tanhf(norm) / fmaxf(norm, 1e-15f);
    v.x *= scale; v.y *= scale; v.z *= scale; v.w *= scale;
    o4[gw * 32 + lane] = v;
}

// ---------------------------------------------------------------------------
extern "C" void kernel_launch(void* const* d_in, const int* in_sizes, int n_in,
                              void* d_out, int out_size) {
    const float* x  = (const float*)d_in[0];
    const int*   ei = (const int*)d_in[1];
    const float* W  = (const float*)d_in[2];
    const float* b  = (const float*)d_in[3];
    float* out = (float*)d_out;

    const int N = in_sizes[0] / DFEAT;
    const int E = in_sizes[1] / 2;

    // 1. zero accumulators
    {
        int n_out = N * DFEAT;
        int grid = (n_out + 255) / 256;
        k_zero<<<grid, 256>>>(out, n_out, N);
    }
    // 2. degrees
    k_degree<<<(E + 255) / 256, 256>>>(ei, E);
    // 3. dinv
    k_dinv<<<(N + 255) / 256, 256>>>(N);
    // 4. logmap0 + GEMM (+bias) -> g_h
    {
        const int SMEM = (128 * WT_STRIDE + 32 * 128) * (int)sizeof(float);
        cudaFuncSetAttribute(k_logmap_gemm,
                             cudaFuncAttributeMaxDynamicSharedMemorySize, SMEM);
        k_logmap_gemm<<<(N + 31) / 32, 256, SMEM>>>(x, W, b, N);
    }
    // 5. gather-scale-scatter over edges (warp per edge, vec4 red)
    {
        long long threads = (long long)E * 32;
        int grid = (int)((threads + 255) / 256);
        k_scatter<<<grid, 256>>>(ei, out, E);
    }
    // 6. expmap0 in place
    k_expmap<<<(N + 7) / 8, 256>>>(out, N);
}

// round 3
// speedup vs baseline: 1.0823x; 1.0823x over previous
#include <cuda_runtime.h>

#define DFEAT 128
#define NMAX  50000
#define WTS   132          // wt row stride (multiple of 4 -> 16B-aligned rows)
#define TILE_R 64

// scratch (no allocations allowed) ------------------------------------------
__device__ __align__(16) float g_h[NMAX * DFEAT];   // pre-scaled features (25.6 MB)
__device__ __align__(16) float g_deg[NMAX];
__device__ __align__(16) float g_dinv[NMAX];

__device__ __forceinline__ void red_add_v4(float* addr, float4 v) {
    asm volatile("red.global.add.v4.f32 [%0], {%1,%2,%3,%4};"
                 :: "l"(addr), "f"(v.x), "f"(v.y), "f"(v.z), "f"(v.w)
                 : "memory");
}

// packed fp32x2 FMA (Blackwell FFMA2) — bit-identical to two FFMAs
__device__ __forceinline__ void ffma2(unsigned long long& d,
                                      unsigned long long a,
                                      unsigned long long b) {
    asm("fma.rn.f32x2 %0, %1, %2, %0;" : "+l"(d) : "l"(a), "l"(b));
}
__device__ __forceinline__ unsigned long long bcast2(float x) {
    unsigned long long r; unsigned xi = __float_as_uint(x);
    asm("mov.b64 %0, {%1, %1};" : "=l"(r) : "r"(xi));
    return r;
}
__device__ __forceinline__ void unpack2(unsigned long long v, float& lo, float& hi) {
    unsigned a, b;
    asm("mov.b64 {%0, %1}, %2;" : "=r"(a), "=r"(b) : "l"(v));
    lo = __uint_as_float(a); hi = __uint_as_float(b);
}

// ---------------------------------------------------------------------------
__global__ void k_zero(float* __restrict__ out, int n_out, int n_nodes) {
    int i = blockIdx.x * blockDim.x + threadIdx.x;
    int stride = gridDim.x * blockDim.x;
    for (int idx = i; idx < n_out; idx += stride) out[idx] = 0.f;
    for (int idx = i; idx < n_nodes; idx += stride) g_deg[idx] = 0.f;
}

__global__ void k_degree(const int* __restrict__ ei, int E) {
    int e = blockIdx.x * blockDim.x + threadIdx.x;
    if (e >= E) return;
    atomicAdd(&g_deg[ei[e]], 1.f);       // src
    atomicAdd(&g_deg[ei[E + e]], 1.f);   // dst
}

__global__ void k_dinv(int N) {
    int i = blockIdx.x * blockDim.x + threadIdx.x;
    if (i < N) g_dinv[i] = rsqrtf(fmaxf(g_deg[i], 1.0f));
}

// ---------------------------------------------------------------------------
// Fused logmap0 + GEMM + bias + dinv scale:
//   g_h[r] = (logmap0(x[r]) @ W^T + b) * dinv[r]
// Block: 256 threads, tile 64 rows x 128 cols. Each thread: 4 rows x 8 cols
// accumulated as 16 f32x2 pairs via fma.rn.f32x2.
__global__ void __launch_bounds__(256, 2)
k_logmap_gemm(const float* __restrict__ x,
              const float* __restrict__ W,
              const float* __restrict__ b, int N) {
    extern __shared__ float sm[];
    float* wt = sm;                  // [128][WTS] transposed W
    float* xs = sm + 128 * WTS;      // [64][128] tangent rows (row-major)
    const int tid  = threadIdx.x;
    const int row0 = blockIdx.x * TILE_R;
    const int warp = tid >> 5, lane = tid & 31;

    // ---- load W transposed (coalesced gmem read) ----
    for (int idx = tid; idx < 128 * 128; idx += 256) {
        int o = idx >> 7, k = idx & 127;
        wt[k * WTS + o] = W[idx];
    }

    // ---- load x rows, logmap0, store to xs (8 warps x 8 rows) ----
    const float4* x4  = (const float4*)x;
    float4*       xs4 = (float4*)xs;
#pragma unroll
    for (int rr = 0; rr < 8; rr++) {
        int r = warp * 8 + rr;
        int row = row0 + r;
        float4 v = (row < N) ? x4[row * 32 + lane] : make_float4(0.f, 0.f, 0.f, 0.f);
        float s = v.x * v.x + v.y * v.y + v.z * v.z + v.w * v.w;
#pragma unroll
        for (int off = 16; off; off >>= 1) s += __shfl_xor_sync(0xFFFFFFFFu, s, off);
        float norm = sqrtf(s);
        float nc = fminf(fmaxf(norm, 1e-15f), 1.0f - 1e-5f);
        float scale = atanhf(nc) / fmaxf(norm, 1e-15f);
        v.x *= scale; v.y *= scale; v.z *= scale; v.w *= scale;
        xs4[r * 32 + lane] = v;
    }
    __syncthreads();

    // ---- GEMM: 4 rows x 8 cols per thread via f32x2 ----
    const int tx = tid & 15;           // col group: cols [4tx..4tx+3] and [64+4tx..]
    const int ty = tid >> 4;           // row group: rows ro..ro+3
    const int c0 = tx * 4;
    const int ro = ty * 4;

    unsigned long long acc[4][4];      // [row][colpair]: pairs (c0,c0+1)(c0+2,c0+3)(c0+64..)(c0+66..)
#pragma unroll
    for (int i = 0; i < 4; i++)
#pragma unroll
        for (int j = 0; j < 4; j++) acc[i][j] = 0ull;

#pragma unroll 2
    for (int k4 = 0; k4 < 128; k4 += 4) {
        float4 xr[4];
#pragma unroll
        for (int i = 0; i < 4; i++)
            xr[i] = *(const float4*)&xs[(ro + i) * 128 + k4];
#pragma unroll
        for (int j = 0; j < 4; j++) {
            int k = k4 + j;
            ulonglong2 wa = *(const ulonglong2*)&wt[k * WTS + c0];
            ulonglong2 wb = *(const ulonglong2*)&wt[k * WTS + c0 + 64];
#pragma unroll
            for (int i = 0; i < 4; i++) {
                float xv = (j == 0) ? xr[i].x : (j == 1) ? xr[i].y : (j == 2) ? xr[i].z : xr[i].w;
                unsigned long long xx = bcast2(xv);
                ffma2(acc[i][0], xx, wa.x);
                ffma2(acc[i][1], xx, wa.y);
                ffma2(acc[i][2], xx, wb.x);
                ffma2(acc[i][3], xx, wb.y);
            }
        }
    }

    // ---- epilogue: +bias, *dinv[row], store ----
    float4 ba = *(const float4*)&b[c0];
    float4 bb = *(const float4*)&b[c0 + 64];
    float4* h4 = (float4*)g_h;
#pragma unroll
    for (int i = 0; i < 4; i++) {
        int row = row0 + ro + i;
        if (row >= N) continue;
        float di = g_dinv[row];
        float4 oa, ob;
        unpack2(acc[i][0], oa.x, oa.y);
        unpack2(acc[i][1], oa.z, oa.w);
        unpack2(acc[i][2], ob.x, ob.y);
        unpack2(acc[i][3], ob.z, ob.w);
        oa.x = (oa.x + ba.x) * di; oa.y = (oa.y + ba.y) * di;
        oa.z = (oa.z + ba.z) * di; oa.w = (oa.w + ba.w) * di;
        ob.x = (ob.x + bb.x) * di; ob.y = (ob.y + bb.y) * di;
        ob.z = (ob.z + bb.z) * di; ob.w = (ob.w + bb.w) * di;
        h4[row * 32 + (c0 >> 2)]      = oa;
        h4[row * 32 + ((c0 + 64) >> 2)] = ob;
    }
}

// ---------------------------------------------------------------------------
// Edge scatter: one warp per edge. lane = one float4 of the 128-dim feature.
// h is pre-scaled by dinv[src], so only dinv[dst] is needed here.
__global__ void k_scatter(const int* __restrict__ ei, float* __restrict__ out, int E) {
    int gw = (blockIdx.x * blockDim.x + threadIdx.x) >> 5;
    int lane = threadIdx.x & 31;
    if (gw >= E) return;
    int src = __ldg(&ei[gw]);
    int dst = __ldg(&ei[E + gw]);
    float coef = g_dinv[dst];
    const float4* h4 = (const float4*)g_h;
    float4 v = h4[src * 32 + lane];
    v.x *= coef; v.y *= coef; v.z *= coef; v.w *= coef;
    float4* o4 = (float4*)out;
    red_add_v4((float*)&o4[dst * 32 + lane], v);
}

// ---------------------------------------------------------------------------
// expmap0 in-place on out: one warp per node.
__global__ void k_expmap(float* __restrict__ out, int N) {
    int gw = (blockIdx.x * blockDim.x + threadIdx.x) >> 5;
    int lane = threadIdx.x & 31;
    if (gw >= N) return;
    float4* o4 = (float4*)out;
    float4 v = o4[gw * 32 + lane];
    float s = v.x * v.x + v.y * v.y + v.z * v.z + v.w * v.w;
#pragma unroll
    for (int off = 16; off; off >>= 1) s += __shfl_xor_sync(0xFFFFFFFFu, s, off);
    float norm = sqrtf(s);
    float scale = tanhf(norm) / fmaxf(norm, 1e-15f);
    v.x *= scale; v.y *= scale; v.z *= scale; v.w *= scale;
    o4[gw * 32 + lane] = v;
}

// ---------------------------------------------------------------------------
extern "C" void kernel_launch(void* const* d_in, const int* in_sizes, int n_in,
                              void* d_out, int out_size) {
    const float* x  = (const float*)d_in[0];
    const int*   ei = (const int*)d_in[1];
    const float* W  = (const float*)d_in[2];
    const float* b  = (const float*)d_in[3];
    float* out = (float*)d_out;

    const int N = in_sizes[0] / DFEAT;
    const int E = in_sizes[1] / 2;

    // 1. zero accumulators
    {
        int n_out = N * DFEAT;
        int grid = (n_out + 255) / 256;
        k_zero<<<grid, 256>>>(out, n_out, N);
    }
    // 2. degrees
    k_degree<<<(E + 255) / 256, 256>>>(ei, E);
    // 3. dinv (must precede GEMM: dinv is fused into the GEMM epilogue)
    k_dinv<<<(N + 255) / 256, 256>>>(N);
    // 4. logmap0 + GEMM (+bias, *dinv) -> g_h
    {
        const int SMEM = (128 * WTS + TILE_R * 128) * (int)sizeof(float);
        cudaFuncSetAttribute(k_logmap_gemm,
                             cudaFuncAttributeMaxDynamicSharedMemorySize, SMEM);
        k_logmap_gemm<<<(N + TILE_R - 1) / TILE_R, 256, SMEM>>>(x, W, b, N);
    }
    // 5. gather-scale-scatter over edges (warp per edge, vec4 red)
    {
        long long threads = (long long)E * 32;
        int grid = (int)((threads + 255) / 256);
        k_scatter<<<grid, 256>>>(ei, out, E);
    }
    // 6. expmap0 in place
    k_expmap<<<(N + 7) / 8, 256>>>(out, N);
}

// round 4
// speedup vs baseline: 1.1856x; 1.0955x over previous
#include <cuda_runtime.h>
#include <cuda_bf16.h>
#include <cstdint>

#define DFEAT 128
#define NMAX  50000
#define BM    64          // rows per block tile
#define LDSK  136         // smem row stride in bf16 units (272 B -> conflict-free LDSM)

// scratch (no allocations allowed) ------------------------------------------
__device__ __align__(16) float g_h[NMAX * DFEAT];   // pre-scaled features (25.6 MB)
__device__ __align__(16) float g_deg[NMAX];
__device__ __align__(16) float g_dinv[NMAX];

__device__ __forceinline__ void red_add_v4(float* addr, float4 v) {
    asm volatile("red.global.add.v4.f32 [%0], {%1,%2,%3,%4};"
                 :: "l"(addr), "f"(v.x), "f"(v.y), "f"(v.z), "f"(v.w)
                 : "memory");
}

__device__ __forceinline__ uint32_t pack_bf2(__nv_bfloat16 lo, __nv_bfloat16 hi) {
    return ((uint32_t)__bfloat16_as_ushort(hi) << 16) | __bfloat16_as_ushort(lo);
}

__device__ __forceinline__ void ldsm_x4(uint32_t addr, uint32_t& r0, uint32_t& r1,
                                        uint32_t& r2, uint32_t& r3) {
    asm volatile("ldmatrix.sync.aligned.m8n8.x4.shared.b16 {%0,%1,%2,%3}, [%4];"
                 : "=r"(r0), "=r"(r1), "=r"(r2), "=r"(r3) : "r"(addr));
}

__device__ __forceinline__ void mma_bf16(float c[4], uint32_t a0, uint32_t a1,
                                         uint32_t a2, uint32_t a3,
                                         uint32_t b0, uint32_t b1) {
    asm volatile("mma.sync.aligned.m16n8k16.row.col.f32.bf16.bf16.f32 "
                 "{%0,%1,%2,%3},{%4,%5,%6,%7},{%8,%9},{%0,%1,%2,%3};"
                 : "+f"(c[0]), "+f"(c[1]), "+f"(c[2]), "+f"(c[3])
                 : "r"(a0), "r"(a1), "r"(a2), "r"(a3), "r"(b0), "r"(b1));
}

// ---------------------------------------------------------------------------
__global__ void k_zero(float* __restrict__ out, int n_out, int n_nodes) {
    int i = blockIdx.x * blockDim.x + threadIdx.x;
    int stride = gridDim.x * blockDim.x;
    for (int idx = i; idx < n_out; idx += stride) out[idx] = 0.f;
    for (int idx = i; idx < n_nodes; idx += stride) g_deg[idx] = 0.f;
}

__global__ void k_degree(const int* __restrict__ ei, int E) {
    int e = blockIdx.x * blockDim.x + threadIdx.x;
    if (e >= E) return;
    atomicAdd(&g_deg[ei[e]], 1.f);       // src
    atomicAdd(&g_deg[ei[E + e]], 1.f);   // dst
}

__global__ void k_dinv(int N) {
    int i = blockIdx.x * blockDim.x + threadIdx.x;
    if (i < N) g_dinv[i] = rsqrtf(fmaxf(g_deg[i], 1.0f));
}

// ---------------------------------------------------------------------------
// Fused logmap0 + GEMM + bias + dinv scale, bf16-split tensor-core path:
//   g_h[r] = (logmap0(x[r]) @ W^T + b) * dinv[r]
// x,W split into bf16 hi/lo; all 4 cross-product MMAs accumulated in fp32.
__global__ void __launch_bounds__(256, 2)
k_logmap_gemm(const float* __restrict__ x,
              const float* __restrict__ W,
              const float* __restrict__ b, int N) {
    extern __shared__ __align__(16) char smraw[];
    __nv_bfloat16* swh = (__nv_bfloat16*)smraw;          // [128][LDSK]
    __nv_bfloat16* swl = swh + 128 * LDSK;
    __nv_bfloat16* sxh = swl + 128 * LDSK;               // [BM][LDSK]
    __nv_bfloat16* sxl = sxh + BM * LDSK;

    const int tid  = threadIdx.x;
    const int warp = tid >> 5, lane = tid & 31;
    const int row0 = blockIdx.x * BM;

    // ---- W -> bf16 hi/lo in smem (coalesced float4 reads) ----
    {
        const float4* W4 = (const float4*)W;    // 128 x 32 float4
        for (int i = tid; i < 128 * 32; i += 256) {
            int n = i >> 5, kc = (i & 31) * 4;
            float4 w = W4[i];
            __nv_bfloat16 h0 = __float2bfloat16_rn(w.x), h1 = __float2bfloat16_rn(w.y);
            __nv_bfloat16 h2 = __float2bfloat16_rn(w.z), h3 = __float2bfloat16_rn(w.w);
            __nv_bfloat16 l0 = __float2bfloat16_rn(w.x - __bfloat162float(h0));
            __nv_bfloat16 l1 = __float2bfloat16_rn(w.y - __bfloat162float(h1));
            __nv_bfloat16 l2 = __float2bfloat16_rn(w.z - __bfloat162float(h2));
            __nv_bfloat16 l3 = __float2bfloat16_rn(w.w - __bfloat162float(h3));
            *(uint2*)&swh[n * LDSK + kc] = make_uint2(pack_bf2(h0, h1), pack_bf2(h2, h3));
            *(uint2*)&swl[n * LDSK + kc] = make_uint2(pack_bf2(l0, l1), pack_bf2(l2, l3));
        }
    }

    // ---- x rows: load, logmap0, split hi/lo (8 warps x 8 rows) ----
    {
        const float4* x4 = (const float4*)x;
#pragma unroll
        for (int rr = 0; rr < 8; rr++) {
            int r = warp * 8 + rr;
            int row = row0 + r;
            float4 v = (row < N) ? x4[row * 32 + lane] : make_float4(0.f, 0.f, 0.f, 0.f);
            float s = v.x * v.x + v.y * v.y + v.z * v.z + v.w * v.w;
#pragma unroll
            for (int off = 16; off; off >>= 1) s += __shfl_xor_sync(0xFFFFFFFFu, s, off);
            float norm = sqrtf(s);
            float nc = fminf(fmaxf(norm, 1e-15f), 1.0f - 1e-5f);
            float scale = atanhf(nc) / fmaxf(norm, 1e-15f);
            v.x *= scale; v.y *= scale; v.z *= scale; v.w *= scale;
            __nv_bfloat16 h0 = __float2bfloat16_rn(v.x), h1 = __float2bfloat16_rn(v.y);
            __nv_bfloat16 h2 = __float2bfloat16_rn(v.z), h3 = __float2bfloat16_rn(v.w);
            __nv_bfloat16 l0 = __float2bfloat16_rn(v.x - __bfloat162float(h0));
            __nv_bfloat16 l1 = __float2bfloat16_rn(v.y - __bfloat162float(h1));
            __nv_bfloat16 l2 = __float2bfloat16_rn(v.z - __bfloat162float(h2));
            __nv_bfloat16 l3 = __float2bfloat16_rn(v.w - __bfloat162float(h3));
            int kc = lane * 4;
            *(uint2*)&sxh[r * LDSK + kc] = make_uint2(pack_bf2(h0, h1), pack_bf2(h2, h3));
            *(uint2*)&sxl[r * LDSK + kc] = make_uint2(pack_bf2(l0, l1), pack_bf2(l2, l3));
        }
    }
    __syncthreads();

    // ---- MMA mainloop ----
    const int wm = warp & 3;           // 0..3 -> m offset
    const int wn = warp >> 2;          // 0..1 -> n offset
    const int m0 = wm * 16;
    const int n0b = wn * 64;

    float acc[8][4];
#pragma unroll
    for (int f = 0; f < 8; f++)
#pragma unroll
        for (int j = 0; j < 4; j++) acc[f][j] = 0.f;

    const int mat = lane >> 3, mr = lane & 7;

#pragma unroll
    for (int kk = 0; kk < 8; kk++) {
        const int k0 = kk * 16;
        // A frags (m16 x k16), hi and lo
        uint32_t ah[4], al[4];
        {
            int arow = m0 + mr + 8 * (mat & 1);
            int acol = k0 + 8 * (mat >> 1);
            uint32_t ad = (uint32_t)__cvta_generic_to_shared(&sxh[arow * LDSK + acol]);
            ldsm_x4(ad, ah[0], ah[1], ah[2], ah[3]);
            uint32_t ad2 = (uint32_t)__cvta_generic_to_shared(&sxl[arow * LDSK + acol]);
            ldsm_x4(ad2, al[0], al[1], al[2], al[3]);
        }
        // B frags: 4 ldsm.x4 each for hi and lo, covering 8 n-frags
        uint32_t bh[4][4], bl[4][4];
#pragma unroll
        for (int g = 0; g < 4; g++) {
            int nrow = n0b + g * 16 + mr + 8 * (mat >> 1);
            int kcol = k0 + 8 * (mat & 1);
            uint32_t bd = (uint32_t)__cvta_generic_to_shared(&swh[nrow * LDSK + kcol]);
            ldsm_x4(bd, bh[g][0], bh[g][1], bh[g][2], bh[g][3]);
            uint32_t bd2 = (uint32_t)__cvta_generic_to_shared(&swl[nrow * LDSK + kcol]);
            ldsm_x4(bd2, bl[g][0], bl[g][1], bl[g][2], bl[g][3]);
        }
#pragma unroll
        for (int f = 0; f < 8; f++) {
            int g = f >> 1, o = (f & 1) * 2;
            uint32_t b0h = bh[g][o], b1h = bh[g][o + 1];
            uint32_t b0l = bl[g][o], b1l = bl[g][o + 1];
            mma_bf16(acc[f], ah[0], ah[1], ah[2], ah[3], b0h, b1h);
            mma_bf16(acc[f], ah[0], ah[1], ah[2], ah[3], b0l, b1l);
            mma_bf16(acc[f], al[0], al[1], al[2], al[3], b0h, b1h);
            mma_bf16(acc[f], al[0], al[1], al[2], al[3], b0l, b1l);
        }
    }

    // ---- epilogue: +bias, *dinv, store float2 pairs ----
    {
        int r0r = row0 + m0 + (lane >> 2);         // first row of frag
        int r1r = r0r + 8;
        float di0 = (r0r < N) ? g_dinv[r0r] : 0.f;
        float di1 = (r1r < N) ? g_dinv[r1r] : 0.f;
        float2* h2p = (float2*)g_h;
#pragma unroll
        for (int f = 0; f < 8; f++) {
            int c = n0b + f * 8 + 2 * (lane & 3);
            float bx = b[c], by = b[c + 1];
            if (r0r < N) {
                float2 o0;
                o0.x = (acc[f][0] + bx) * di0;
                o0.y = (acc[f][1] + by) * di0;
                h2p[(r0r * DFEAT + c) >> 1] = o0;
            }
            if (r1r < N) {
                float2 o1;
                o1.x = (acc[f][2] + bx) * di1;
                o1.y = (acc[f][3] + by) * di1;
                h2p[(r1r * DFEAT + c) >> 1] = o1;
            }
        }
    }
}

// ---------------------------------------------------------------------------
// Edge scatter: one warp per edge. lane = one float4 of the 128-dim feature.
// h is pre-scaled by dinv[src], so only dinv[dst] is needed here.
__global__ void k_scatter(const int* __restrict__ ei, float* __restrict__ out, int E) {
    int gw = (blockIdx.x * blockDim.x + threadIdx.x) >> 5;
    int lane = threadIdx.x & 31;
    if (gw >= E) return;
    int src = __ldg(&ei[gw]);
    int dst = __ldg(&ei[E + gw]);
    float coef = g_dinv[dst];
    const float4* h4 = (const float4*)g_h;
    float4 v = h4[src * 32 + lane];
    v.x *= coef; v.y *= coef; v.z *= coef; v.w *= coef;
    float4* o4 = (float4*)out;
    red_add_v4((float*)&o4[dst * 32 + lane], v);
}

// ---------------------------------------------------------------------------
// expmap0 in-place on out: one warp per node.
__global__ void k_expmap(float* __restrict__ out, int N) {
    int gw = (blockIdx.x * blockDim.x + threadIdx.x) >> 5;
    int lane = threadIdx.x & 31;
    if (gw >= N) return;
    float4* o4 = (float4*)out;
    float4 v = o4[gw * 32 + lane];
    float s = v.x * v.x + v.y * v.y + v.z * v.z + v.w * v.w;
#pragma unroll
    for (int off = 16; off; off >>= 1) s += __shfl_xor_sync(0xFFFFFFFFu, s, off);
    float norm = sqrtf(s);
    float scale = tanhf(norm) / fmaxf(norm, 1e-15f);
    v.x *= scale; v.y *= scale; v.z *= scale; v.w *= scale;
    o4[gw * 32 + lane] = v;
}

// ---------------------------------------------------------------------------
extern "C" void kernel_launch(void* const* d_in, const int* in_sizes, int n_in,
                              void* d_out, int out_size) {
    const float* x  = (const float*)d_in[0];
    const int*   ei = (const int*)d_in[1];
    const float* W  = (const float*)d_in[2];
    const float* b  = (const float*)d_in[3];
    float* out = (float*)d_out;

    const int N = in_sizes[0] / DFEAT;
    const int E = in_sizes[1] / 2;

    // 1. zero accumulators
    {
        int n_out = N * DFEAT;
        int grid = (n_out + 255) / 256;
        k_zero<<<grid, 256>>>(out, n_out, N);
    }
    // 2. degrees
    k_degree<<<(E + 255) / 256, 256>>>(ei, E);
    // 3. dinv (must precede GEMM: fused into GEMM epilogue)
    k_dinv<<<(N + 255) / 256, 256>>>(N);
    // 4. logmap0 + GEMM (+bias, *dinv) -> g_h   [bf16-split tensor cores]
    {
        const int SMEM = (2 * 128 * LDSK + 2 * BM * LDSK) * (int)sizeof(__nv_bfloat16);
        cudaFuncSetAttribute(k_logmap_gemm,
                             cudaFuncAttributeMaxDynamicSharedMemorySize, SMEM);
        k_logmap_gemm<<<(N + BM - 1) / BM, 256, SMEM>>>(x, W, b, N);
    }
    // 5. gather-scale-scatter over edges (warp per edge, vec4 red)
    {
        long long threads = (long long)E * 32;
        int grid = (int)((threads + 255) / 256);
        k_scatter<<<grid, 256>>>(ei, out, E);
    }
    // 6. expmap0 in place
    k_expmap<<<(N + 7) / 8, 256>>>(out, N);
}